// round 8
// baseline (speedup 1.0000x reference)
#include <cuda_runtime.h>
#include <cuda_bf16.h>
#include <math.h>

// ---------------------------------------------------------------------------
// Causal self-attention block via mma.sync (HMMA bf16) on sm_103.
// fp32 emulation by 3-term bf16 split along K (k' = 3k + {0,1,2}):
//   A3 = (Ah, Al, Ah),  B3 = (Bh, Bh, Bl)  -> drops only Al*Bl (~2^-18).
// R8: 3-stage cp.async pipeline, ONE barrier per 64-element k-chunk
// (stage being overwritten was consumed 2 iterations ago).
// ---------------------------------------------------------------------------

static const int Bb = 4, T = 2048, C = 1024;
static const int M = Bb * T;          // 8192
static const int K3C = 3 * C;         // 3072
static const int K3T = 3 * T;         // 6144

// fp32 intermediates
__device__ float g_att[(size_t)4 * 2048 * 2048];
__device__ float g_v  [(size_t)8192 * 1024];
// 3-split bf16 operands
__device__ __nv_bfloat16 g_x3    [(size_t)8192 * 3072];
__device__ __nv_bfloat16 g_wqkv3 [(size_t)3072 * 3072];
__device__ __nv_bfloat16 g_wproj3[(size_t)1024 * 3072];
__device__ __nv_bfloat16 g_q3    [(size_t)8192 * 3072];
__device__ __nv_bfloat16 g_k3    [(size_t)8192 * 3072];
__device__ __nv_bfloat16 g_vt3   [(size_t)4 * 1024 * 6144];
__device__ __nv_bfloat16 g_att3  [(size_t)8192 * 6144];
__device__ __nv_bfloat16 g_o3    [(size_t)8192 * 3072];

__device__ __forceinline__ void cp_async16(unsigned s, const void* g) {
    asm volatile("cp.async.cg.shared.global [%0], [%1], 16;"
        :: "r"(s), "l"(__cvta_generic_to_global(g)) : "memory");
}
__device__ __forceinline__ void ldm4(unsigned* r, unsigned addr) {
    asm volatile("ldmatrix.sync.aligned.m8n8.x4.shared.b16 {%0,%1,%2,%3}, [%4];"
        : "=r"(r[0]), "=r"(r[1]), "=r"(r[2]), "=r"(r[3]) : "r"(addr));
}
__device__ __forceinline__ void mma16816(float* d, const unsigned* a,
                                         unsigned b0, unsigned b1) {
    asm volatile(
        "mma.sync.aligned.m16n8k16.row.col.f32.bf16.bf16.f32 "
        "{%0,%1,%2,%3}, {%4,%5,%6,%7}, {%8,%9}, {%0,%1,%2,%3};"
        : "+f"(d[0]), "+f"(d[1]), "+f"(d[2]), "+f"(d[3])
        : "r"(a[0]), "r"(a[1]), "r"(a[2]), "r"(a[3]), "r"(b0), "r"(b1));
}

// pack (vx, vy) as 3-term split -> 3 u32 stores (12B)
// satype=1: (h,l,h)(h2,l2,h2)   satype=0: (h,h,l)(h2,h2,l2)
__device__ __forceinline__ void store3(__nv_bfloat16* p, float vx, float vy,
                                       int satype) {
    __nv_bfloat16 hx = __float2bfloat16(vx);
    __nv_bfloat16 lx = __float2bfloat16(vx - __bfloat162float(hx));
    __nv_bfloat16 hy = __float2bfloat16(vy);
    __nv_bfloat16 ly = __float2bfloat16(vy - __bfloat162float(hy));
    unsigned hxu = __bfloat16_as_ushort(hx), lxu = __bfloat16_as_ushort(lx);
    unsigned hyu = __bfloat16_as_ushort(hy), lyu = __bfloat16_as_ushort(ly);
    unsigned u0, u1, u2;
    if (satype) { u0 = hxu | (lxu << 16); u1 = hxu | (hyu << 16); u2 = lyu | (hyu << 16); }
    else        { u0 = hxu | (hxu << 16); u1 = lxu | (hyu << 16); u2 = hyu | (lyu << 16); }
    unsigned* up = (unsigned*)p;
    up[0] = u0; up[1] = u1; up[2] = u2;
}

#define BKC 64            // bf16 elements per k-chunk (4 k16 slices)
#define STAGE_BYTES 32768 // A 16KB + B 16KB
#define NSTG 3
#define GEMM_SMEM (NSTG * STAGE_BYTES)   // 96KB

// SW128 on 128-byte rows: chunk index c (0..7) -> c ^ (r & 7)
#define SWB(r, c) ((unsigned)((r) * 128 + ((((c) ^ ((r) & 7)) & 7) << 4)))

// ---------------------------------------------------------------------------
// D[M,N] = alpha * A3[M,K'] . B3[N,K']^T (+ bias)   (both operands K-major)
// 128 threads, 4 warps, 64x64 warp tiles over a 128x128 CTA tile.
// emode 0: fp32 out (Cf, ldcf)          [scores, proj]
// emode 1: A-split bf16 out (C3a, ldc3) [att@V -> o3]
// emode 2: qkv triple: col<1024 -> q3 (A-split), <2048 -> k3 (B-split),
//          else fp32 -> Cv (ld 1024). bias indexed by absolute col.
// ---------------------------------------------------------------------------
__global__ void __launch_bounds__(128, 2)
hmma_gemm(const __nv_bfloat16* __restrict__ A, const __nv_bfloat16* __restrict__ B,
          float* __restrict__ Cf, __nv_bfloat16* __restrict__ C3a,
          __nv_bfloat16* __restrict__ C3b, float* __restrict__ Cv,
          int lda, int ldb, int ldcf, int ldc3,
          long long sA, long long sB, long long sC,
          float alpha, const float* __restrict__ bias,
          int causal_skip, int klimit, int K3, int emode)
{
    const int row0 = blockIdx.y * 128;
    const int col0 = blockIdx.x * 128;
    if (causal_skip && col0 > row0) return;              // strictly-upper tiles
    const int kend = klimit ? min(K3, 3 * (row0 + 128)) : K3;
    const int nch = kend / BKC;

    A += (long long)blockIdx.z * sA + (long long)row0 * lda;
    B += (long long)blockIdx.z * sB + (long long)col0 * ldb;

    extern __shared__ __align__(128) unsigned char smem[];
    const unsigned sb = (unsigned)__cvta_generic_to_shared(smem);

    const int tid = threadIdx.x;
    const int lane = tid & 31;
    const int wid = tid >> 5;          // 0..3
    const int wm = wid >> 1;           // 0..1 -> 64-row half
    const int wn = wid & 1;            // 0..1 -> 64-col half

    float acc[4][8][4];
    #pragma unroll
    for (int i = 0; i < 4; i++)
        #pragma unroll
        for (int j = 0; j < 8; j++)
            #pragma unroll
            for (int k = 0; k < 4; k++) acc[i][j][k] = 0.f;

    // tile loader: 128 rows x 64 bf16 per operand, 8 x 16B per row
    const int lr0 = tid >> 3;        // advances by 16 per iter
    const int lc  = tid & 7;
    auto load_tile = [&](int st, int kc) {
        const unsigned sA_ = sb + st * STAGE_BYTES;
        const unsigned sB_ = sA_ + 16384;
        #pragma unroll
        for (int p = 0; p < 8; p++) {
            const int r = lr0 + p * 16;
            const unsigned so = SWB(r, lc);
            cp_async16(sA_ + so, A + (long long)r * lda + kc + lc * 8);
            cp_async16(sB_ + so, B + (long long)r * ldb + kc + lc * 8);
        }
        asm volatile("cp.async.commit_group;" ::: "memory");
    };

    // fragment loaders for k16 slice j (0..3)
    auto ld_afr = [&](unsigned sA_, int j, unsigned af[4][4]) {
        const int ch = 2 * j + (lane >> 4);
        #pragma unroll
        for (int mb = 0; mb < 4; mb++) {
            const int mr = wm * 64 + mb * 16 + (lane & 15);
            ldm4(af[mb], sA_ + SWB(mr, ch));
        }
    };
    auto ld_bfr = [&](unsigned sB_, int j, unsigned bf[4][4]) {
        const int ch = 2 * j + (lane >> 4);
        #pragma unroll
        for (int nbb = 0; nbb < 4; nbb++) {
            const int nr = wn * 64 + nbb * 16 + (lane & 15);
            ldm4(bf[nbb], sB_ + SWB(nr, ch));
        }
    };

    auto compute = [&](int st) {
        const unsigned sA_ = sb + st * STAGE_BYTES;
        const unsigned sB_ = sA_ + 16384;
        unsigned af[2][4][4], bf[2][4][4];
        ld_afr(sA_, 0, af[0]);
        ld_bfr(sB_, 0, bf[0]);
        #pragma unroll
        for (int j = 0; j < 4; j++) {
            const int cur = j & 1;
            if (j < 3) {                       // prefetch next slice's frags
                ld_afr(sA_, j + 1, af[cur ^ 1]);
                ld_bfr(sB_, j + 1, bf[cur ^ 1]);
            }
            #pragma unroll
            for (int mb = 0; mb < 4; mb++)
                #pragma unroll
                for (int nbb = 0; nbb < 4; nbb++) {
                    mma16816(acc[mb][nbb * 2 + 0], af[cur][mb],
                             bf[cur][nbb][0], bf[cur][nbb][2]);
                    mma16816(acc[mb][nbb * 2 + 1], af[cur][mb],
                             bf[cur][nbb][1], bf[cur][nbb][3]);
                }
        }
    };

    // 3-stage: prologue loads chunks 0,1; per-iter: wait(i) -> barrier ->
    // load(i+2) into stage (i-1)%3 (consumed 2 iters ago) -> compute(i).
    load_tile(0, 0);
    if (nch > 1) load_tile(1, BKC);
    for (int i = 0; i < nch; i++) {
        if (i + 1 < nch) asm volatile("cp.async.wait_group 1;" ::: "memory");
        else             asm volatile("cp.async.wait_group 0;" ::: "memory");
        __syncthreads();
        const int nx = i + 2;
        if (nx < nch) load_tile(nx % NSTG, nx * BKC);
        compute(i % NSTG);
    }

    // ----- epilogue -----
    __nv_bfloat16* d3 = 0;
    int satype = 1, colr = col0;
    float* df = 0;
    int ldf = ldcf;
    if (emode == 0) {
        df = Cf + (long long)blockIdx.z * sC;
    } else if (emode == 1) {
        d3 = C3a + (long long)blockIdx.z * sC;
    } else {                                  // qkv triple
        if (col0 < 1024)      { d3 = C3a; satype = 1; colr = col0; }
        else if (col0 < 2048) { d3 = C3b; satype = 0; colr = col0 - 1024; }
        else                  { df = Cv; ldf = 1024; colr = col0 - 2048; }
    }

    const int cbase = wn * 64 + 2 * (lane & 3);
    #pragma unroll
    for (int mb = 0; mb < 4; mb++) {
        #pragma unroll
        for (int half = 0; half < 2; half++) {
            const int r = row0 + wm * 64 + mb * 16 + (lane >> 2) + half * 8;
            #pragma unroll
            for (int nb = 0; nb < 8; nb++) {
                const int cr = colr + cbase + nb * 8;    // region-relative (even)
                const int ca = col0 + cbase + nb * 8;    // absolute (bias)
                float vx = acc[mb][nb][half * 2 + 0] * alpha;
                float vy = acc[mb][nb][half * 2 + 1] * alpha;
                if (bias) { vx += bias[ca]; vy += bias[ca + 1]; }
                if (d3) store3(d3 + (long long)r * ldc3 + 3 * cr, vx, vy, satype);
                else    *(float2*)(df + (long long)r * ldf + cr) = make_float2(vx, vy);
            }
        }
    }
}

// ---------------------------------------------------------------------------
// fp32 -> 3-term interleaved bf16 split (standalone; inputs only)
// ---------------------------------------------------------------------------
template <int ATYPE>
__global__ void split3_kernel(const float* __restrict__ in,
                              __nv_bfloat16* __restrict__ out,
                              int R, int Cin, int ld)
{
    const int c8n = Cin >> 3;
    long long idx = (long long)blockIdx.x * blockDim.x + threadIdx.x;
    if (idx >= (long long)R * c8n) return;
    const int r = (int)(idx / c8n);
    const int c = (int)(idx - (long long)r * c8n) * 8;

    const float4 v0 = *(const float4*)(in + (long long)r * ld + c);
    const float4 v1 = *(const float4*)(in + (long long)r * ld + c + 4);
    float f[8] = {v0.x, v0.y, v0.z, v0.w, v1.x, v1.y, v1.z, v1.w};

    alignas(16) unsigned short s[24];
    #pragma unroll
    for (int j = 0; j < 8; j++) {
        __nv_bfloat16 h = __float2bfloat16(f[j]);
        __nv_bfloat16 l = __float2bfloat16(f[j] - __bfloat162float(h));
        unsigned short hu = __bfloat16_as_ushort(h);
        unsigned short lu = __bfloat16_as_ushort(l);
        if (ATYPE) { s[3*j] = hu; s[3*j+1] = lu; s[3*j+2] = hu; }
        else       { s[3*j] = hu; s[3*j+1] = hu; s[3*j+2] = lu; }
    }
    __nv_bfloat16* op = out + (long long)r * (3 * Cin) + 3 * c;
    *(uint4*)(op)      = *(uint4*)(s);
    *(uint4*)(op + 8)  = *(uint4*)(s + 8);
    *(uint4*)(op + 16) = *(uint4*)(s + 16);
}

// V[s,c] fp32 [8192,1024] -> vt3[b][c][3s+{0,1,2}] = (hi,hi,lo)
__global__ void transpose_split3_kernel(const float* __restrict__ v,
                                        __nv_bfloat16* __restrict__ vt3)
{
    __shared__ float tile[32][33];
    const int b = blockIdx.z;
    const int s0 = blockIdx.x * 32, c0 = blockIdx.y * 32;
    const int tx = threadIdx.x, ty = threadIdx.y;
    tile[ty][tx] = v[((long long)(b * 2048 + s0 + ty)) * 1024 + c0 + tx];
    __syncthreads();
    const float val = tile[tx][ty];
    __nv_bfloat16 h = __float2bfloat16(val);
    __nv_bfloat16 l = __float2bfloat16(val - __bfloat162float(h));
    __nv_bfloat16* op = vt3 + ((long long)(b * 1024 + c0 + ty)) * 6144 + 3 * (s0 + tx);
    op[0] = h; op[1] = h; op[2] = l;
}

// ---------------------------------------------------------------------------
// FMA-pipe exp for x <= 0 (MUFU EX2 is quarter-rate on B300).
// ---------------------------------------------------------------------------
__device__ __forceinline__ float fexp(float x) {
    float y = x * 1.4426950408889634f;
    float n = floorf(y);
    float f = y - n;
    float p = 0.000154035304f;
    p = fmaf(p, f, 0.00133335581f);
    p = fmaf(p, f, 0.00961812910f);
    p = fmaf(p, f, 0.0555041087f);
    p = fmaf(p, f, 0.240226507f);
    p = fmaf(p, f, 0.693147180f);
    p = fmaf(p, f, 1.0f);
    int ni = (int)n;
    if (ni < -126) return 0.f;
    return p * __int_as_float((ni + 127) << 23);
}

// ---------------------------------------------------------------------------
// causal softmax: reads fp32 scores, writes A-split bf16 att3 (zeros tail)
// ---------------------------------------------------------------------------
__global__ void softmax_split_kernel(const float* __restrict__ att,
                                     __nv_bfloat16* __restrict__ att3, int Tn)
{
    __shared__ float buf[2048];
    __shared__ float red[256];
    const int row = blockIdx.x;
    const int t = row % Tn;
    const float* p = att + (long long)row * Tn;
    const int tid = threadIdx.x;
    const int len = t + 1;

    float m = -1e30f;
    for (int s = tid; s < len; s += 256) { float v = p[s]; buf[s] = v; m = fmaxf(m, v); }
    red[tid] = m; __syncthreads();
    for (int off = 128; off > 0; off >>= 1) {
        if (tid < off) red[tid] = fmaxf(red[tid], red[tid + off]);
        __syncthreads();
    }
    m = red[0]; __syncthreads();

    float sum = 0.f;
    for (int s = tid; s < len; s += 256) {
        float e = fexp(buf[s] - m);
        buf[s] = e;
        sum += e;
    }
    red[tid] = sum; __syncthreads();
    for (int off = 128; off > 0; off >>= 1) {
        if (tid < off) red[tid] += red[tid + off];
        __syncthreads();
    }
    const float inv = 1.f / red[0];
    __syncthreads();

    __nv_bfloat16* out = att3 + (long long)row * (3 * Tn);
    const int s8 = tid * 8;
    alignas(16) unsigned short sh[24];
    #pragma unroll
    for (int j = 0; j < 8; j++) {
        const int s = s8 + j;
        const float e = (s < len) ? buf[s] * inv : 0.f;
        __nv_bfloat16 h = __float2bfloat16(e);
        __nv_bfloat16 l = __float2bfloat16(e - __bfloat162float(h));
        sh[3*j] = __bfloat16_as_ushort(h);
        sh[3*j+1] = __bfloat16_as_ushort(l);
        sh[3*j+2] = __bfloat16_as_ushort(h);
    }
    __nv_bfloat16* op = out + 3 * s8;
    *(uint4*)(op)      = *(uint4*)(sh);
    *(uint4*)(op + 8)  = *(uint4*)(sh + 8);
    *(uint4*)(op + 16) = *(uint4*)(sh + 16);
}

// ---------------------------------------------------------------------------
extern "C" void kernel_launch(void* const* d_in, const int* in_sizes, int n_in,
                              void* d_out, int out_size)
{
    const float* x      = (const float*)d_in[0];
    const float* w_qkv  = (const float*)d_in[1];
    const float* b_qkv  = (const float*)d_in[2];
    const float* w_proj = (const float*)d_in[3];
    const float* b_proj = (const float*)d_in[4];
    float* out = (float*)d_out;

    float *att, *v;
    __nv_bfloat16 *x3, *wqkv3, *wproj3, *q3, *k3, *vt3, *att3, *o3;
    cudaGetSymbolAddress((void**)&att, g_att);
    cudaGetSymbolAddress((void**)&v,   g_v);
    cudaGetSymbolAddress((void**)&x3,    g_x3);
    cudaGetSymbolAddress((void**)&wqkv3, g_wqkv3);
    cudaGetSymbolAddress((void**)&wproj3,g_wproj3);
    cudaGetSymbolAddress((void**)&q3,    g_q3);
    cudaGetSymbolAddress((void**)&k3,    g_k3);
    cudaGetSymbolAddress((void**)&vt3,   g_vt3);
    cudaGetSymbolAddress((void**)&att3,  g_att3);
    cudaGetSymbolAddress((void**)&o3,    g_o3);

    cudaFuncSetAttribute(hmma_gemm,
        cudaFuncAttributeMaxDynamicSharedMemorySize, GEMM_SMEM);

    const float inv_sqrt_c = 0.03125f;

    // split the raw inputs
    split3_kernel<1><<<(M * (C / 8) + 255) / 256, 256>>>(x, x3, M, C, C);
    split3_kernel<0><<<(3 * C * (C / 8) + 255) / 256, 256>>>(w_qkv, wqkv3, 3 * C, C, C);
    split3_kernel<0><<<(C * (C / 8) + 255) / 256, 256>>>(w_proj, wproj3, C, C, C);

    // 1) qkv GEMM, fused epilogue -> q3 (A-split) / k3 (B-split) / v (fp32)
    hmma_gemm<<<dim3(3 * C / 128, M / 128, 1), 128, GEMM_SMEM>>>(
        x3, wqkv3, nullptr, q3, k3, v,
        K3C, K3C, 0, K3C, 0, 0, 0,
        1.f, b_qkv, 0, 0, K3C, 2);

    // transpose-split v -> vt3 (B-type)
    transpose_split3_kernel<<<dim3(T / 32, C / 32, Bb), dim3(32, 32)>>>(v, vt3);

    // 2) scores = (q @ k^T) / sqrt(C), causal tile-skip, fp32 out
    hmma_gemm<<<dim3(T / 128, T / 128, Bb), 128, GEMM_SMEM>>>(
        q3, k3, att, nullptr, nullptr, nullptr,
        K3C, K3C, T, 0,
        (long long)T * K3C, (long long)T * K3C, (long long)T * T,
        inv_sqrt_c, nullptr, 1, 0, K3C, 0);

    // 3) softmax fused with A-split -> att3 (zeros masked tail)
    softmax_split_kernel<<<M, 256>>>(att, att3, T);

    // 4) o = att @ V  (k-limited), fused epilogue -> o3 (A-split)
    hmma_gemm<<<dim3(C / 128, T / 128, Bb), 128, GEMM_SMEM>>>(
        att3, vt3, nullptr, o3, nullptr, nullptr,
        K3T, K3T, 0, K3C,
        (long long)T * K3T, (long long)C * K3T, (long long)T * K3C,
        1.f, nullptr, 0, 1, K3T, 1);

    // 5) out = o @ w_proj^T + b_proj   (fp32 out)
    hmma_gemm<<<dim3(C / 128, M / 128, 1), 128, GEMM_SMEM>>>(
        o3, wproj3, out, nullptr, nullptr, nullptr,
        K3C, K3C, C, 0, 0, 0, 0,
        1.f, b_proj, 0, 0, K3C, 0);
}

// round 9
// speedup vs baseline: 1.1204x; 1.1204x over previous
#include <cuda_runtime.h>
#include <cuda_bf16.h>
#include <math.h>

// ---------------------------------------------------------------------------
// Causal self-attention block via mma.sync (HMMA bf16) on sm_103.
// fp32 emulation by 3-term bf16 split along K (k' = 3k + {0,1,2}):
//   A3 = (Ah, Al, Ah),  B3 = (Bh, Bh, Bl)  -> drops only Al*Bl (~2^-18).
// R9: all split operands stored PRE-SWIZZLED in contiguous 16KB tiles
// ([128 rows x 64 k']); GEMM stages loaded with cp.async.bulk (1 instr per
// 16KB tile) + mbarrier complete_tx, eliminating the LDGSTS LSU bottleneck.
// ---------------------------------------------------------------------------

static const int Bb = 4, T = 2048, C = 1024;
static const int M = Bb * T;          // 8192
static const int K3C = 3 * C;         // 3072 (48 chunks)
static const int K3T = 3 * T;         // 6144 (96 chunks)

#define TILE_BYTES 16384              // 128 rows x 64 bf16

// fp32 intermediates
__device__ float g_att[(size_t)4 * 2048 * 2048];
__device__ float g_v  [(size_t)8192 * 1024];
// 3-split bf16 operands, tiled layout: [row_tile][chunk][16KB swizzled tile]
__device__ __nv_bfloat16 g_x3    [(size_t)8192 * 3072];
__device__ __nv_bfloat16 g_wqkv3 [(size_t)3072 * 3072];
__device__ __nv_bfloat16 g_wproj3[(size_t)1024 * 3072];
__device__ __nv_bfloat16 g_q3    [(size_t)8192 * 3072];
__device__ __nv_bfloat16 g_k3    [(size_t)8192 * 3072];
__device__ __nv_bfloat16 g_vt3   [(size_t)4 * 1024 * 6144];
__device__ __nv_bfloat16 g_att3  [(size_t)8192 * 6144];
__device__ __nv_bfloat16 g_o3    [(size_t)8192 * 3072];

// SW128 on 128-byte k-lines: 16B chunk index c (0..7) -> c ^ (r & 7)
#define SWB(r, c) ((unsigned)((r) * 128 + ((((c) ^ ((r) & 7)) & 7) << 4)))

__device__ __forceinline__ void ldm4(unsigned* r, unsigned addr) {
    asm volatile("ldmatrix.sync.aligned.m8n8.x4.shared.b16 {%0,%1,%2,%3}, [%4];"
        : "=r"(r[0]), "=r"(r[1]), "=r"(r[2]), "=r"(r[3]) : "r"(addr));
}
__device__ __forceinline__ void mma16816(float* d, const unsigned* a,
                                         unsigned b0, unsigned b1) {
    asm volatile(
        "mma.sync.aligned.m16n8k16.row.col.f32.bf16.bf16.f32 "
        "{%0,%1,%2,%3}, {%4,%5,%6,%7}, {%8,%9}, {%0,%1,%2,%3};"
        : "+f"(d[0]), "+f"(d[1]), "+f"(d[2]), "+f"(d[3])
        : "r"(a[0]), "r"(a[1]), "r"(a[2]), "r"(a[3]), "r"(b0), "r"(b1));
}
__device__ __forceinline__ void bulk16k(unsigned sdst, const void* g, unsigned mb) {
    unsigned sz = TILE_BYTES;
    asm volatile(
        "cp.async.bulk.shared::cluster.global.mbarrier::complete_tx::bytes "
        "[%0], [%1], %2, [%3];"
        :: "r"(sdst), "l"(__cvta_generic_to_global(g)), "r"(sz), "r"(mb)
        : "memory");
}
__device__ __forceinline__ void mbar_wait(unsigned mbar, unsigned parity) {
    asm volatile(
        "{\n\t.reg .pred P;\n\t"
        "LW_%=:\n\t"
        "mbarrier.try_wait.parity.acquire.cta.shared::cta.b64 P, [%0], %1, 0x989680;\n\t"
        "@P bra.uni LD_%=;\n\t"
        "bra.uni LW_%=;\n\t"
        "LD_%=:\n\t}"
        :: "r"(mbar), "r"(parity) : "memory");
}

// write (vx, vy) as 3-term split into a tiled+swizzled row: k' base = 3*cr
// satype=1: (h,l,h)   satype=0: (h,h,l)
__device__ __forceinline__ void store3_tiled(char* rowbase, int lr, int cr,
                                             float vx, float vy, int satype) {
    __nv_bfloat16 hx = __float2bfloat16(vx);
    __nv_bfloat16 lx = __float2bfloat16(vx - __bfloat162float(hx));
    __nv_bfloat16 hy = __float2bfloat16(vy);
    __nv_bfloat16 ly = __float2bfloat16(vy - __bfloat162float(hy));
    unsigned hxu = __bfloat16_as_ushort(hx), lxu = __bfloat16_as_ushort(lx);
    unsigned hyu = __bfloat16_as_ushort(hy), lyu = __bfloat16_as_ushort(ly);
    unsigned u[3];
    if (satype) { u[0] = hxu | (lxu << 16); u[1] = hxu | (hyu << 16); u[2] = lyu | (hyu << 16); }
    else        { u[0] = hxu | (hxu << 16); u[1] = lxu | (hyu << 16); u[2] = hyu | (lyu << 16); }
    #pragma unroll
    for (int j = 0; j < 3; j++) {
        const int byte = 6 * cr + 4 * j;
        const int ct = byte >> 7;              // chunk tile along k'
        const int rem = byte & 127;
        *(unsigned*)(rowbase + (size_t)ct * TILE_BYTES
                     + SWB(lr, rem >> 4) + (rem & 15)) = u[j];
    }
}

#define BKC 64            // bf16 elements per k-chunk (4 k16 slices)
#define STAGE_BYTES 32768 // A 16KB + B 16KB
#define NSTG 3
#define GEMM_SMEM (NSTG * STAGE_BYTES + 128)

// ---------------------------------------------------------------------------
// D[M,N] = alpha * A3 . B3^T (+ bias); A3/B3 are tiled split-bf16 buffers.
// 128 threads, 4 warps, 64x64 warp tiles over a 128x128 CTA tile.
// ncha/nchb: chunks per row-stripe of each buffer; sAt/sBt: batch strides in
// tiles; nchc/sCt: same for tiled output (emodes 1,2).
// emode 0: fp32 out (Cf, ldcf, sC elems)   [scores, proj]
// emode 1: A-split tiled out C3a           [att@V -> o3]
// emode 2: qkv triple: col<1024 -> C3a (A-split), <2048 -> C3b (B-split),
//          else fp32 -> Cv (ld 1024). bias indexed by absolute col.
// ---------------------------------------------------------------------------
__global__ void __launch_bounds__(128, 2)
hmma_gemm(const char* __restrict__ A, const char* __restrict__ B,
          float* __restrict__ Cf, char* __restrict__ C3a,
          char* __restrict__ C3b, float* __restrict__ Cv,
          int ncha, int nchb, int ldcf, int nchc,
          long long sAt, long long sBt, long long sC,
          float alpha, const float* __restrict__ bias,
          int causal_skip, int klimit, int K3, int emode)
{
    const int row0 = blockIdx.y * 128;
    const int col0 = blockIdx.x * 128;
    if (causal_skip && col0 > row0) return;              // strictly-upper tiles
    const int kend = klimit ? min(K3, 3 * (row0 + 128)) : K3;
    const int nch = kend / BKC;

    A += ((long long)blockIdx.z * sAt + (long long)(row0 >> 7) * ncha) * TILE_BYTES;
    B += ((long long)blockIdx.z * sBt + (long long)(col0 >> 7) * nchb) * TILE_BYTES;

    extern __shared__ __align__(128) unsigned char smem[];
    const unsigned sb = (unsigned)__cvta_generic_to_shared(smem);
    const unsigned mb0 = sb + NSTG * STAGE_BYTES;        // 3 mbarriers

    const int tid = threadIdx.x;
    const int lane = tid & 31;
    const int wid = tid >> 5;          // 0..3
    const int wm = wid >> 1;           // 0..1 -> 64-row half
    const int wn = wid & 1;            // 0..1 -> 64-col half

    if (tid == 0) {
        #pragma unroll
        for (int s = 0; s < NSTG; s++)
            asm volatile("mbarrier.init.shared.b64 [%0], 1;"
                         :: "r"(mb0 + 8 * s) : "memory");
    }
    __syncthreads();

    float acc[4][8][4];
    #pragma unroll
    for (int i = 0; i < 4; i++)
        #pragma unroll
        for (int j = 0; j < 8; j++)
            #pragma unroll
            for (int k = 0; k < 4; k++) acc[i][j][k] = 0.f;

    auto bulk_load = [&](int st, int chunk) {
        if (tid == 0) {
            const unsigned mb = mb0 + 8 * st;
            asm volatile("mbarrier.arrive.expect_tx.shared.b64 _, [%0], %1;"
                         :: "r"(mb), "r"(2u * TILE_BYTES) : "memory");
            const unsigned sA_ = sb + st * STAGE_BYTES;
            bulk16k(sA_,         A + (size_t)chunk * TILE_BYTES, mb);
            bulk16k(sA_ + TILE_BYTES, B + (size_t)chunk * TILE_BYTES, mb);
        }
    };

    // fragment loaders for k16 slice j (0..3)
    auto ld_afr = [&](unsigned sA_, int j, unsigned af[4][4]) {
        const int ch = 2 * j + (lane >> 4);
        #pragma unroll
        for (int mb = 0; mb < 4; mb++) {
            const int mr = wm * 64 + mb * 16 + (lane & 15);
            ldm4(af[mb], sA_ + SWB(mr, ch));
        }
    };
    auto ld_bfr = [&](unsigned sB_, int j, unsigned bf[4][4]) {
        const int ch = 2 * j + (lane >> 4);
        #pragma unroll
        for (int nbb = 0; nbb < 4; nbb++) {
            const int nr = wn * 64 + nbb * 16 + (lane & 15);
            ldm4(bf[nbb], sB_ + SWB(nr, ch));
        }
    };

    auto compute = [&](int st) {
        const unsigned sA_ = sb + st * STAGE_BYTES;
        const unsigned sB_ = sA_ + TILE_BYTES;
        unsigned af[2][4][4], bf[2][4][4];
        ld_afr(sA_, 0, af[0]);
        ld_bfr(sB_, 0, bf[0]);
        #pragma unroll
        for (int j = 0; j < 4; j++) {
            const int cur = j & 1;
            if (j < 3) {                       // prefetch next slice's frags
                ld_afr(sA_, j + 1, af[cur ^ 1]);
                ld_bfr(sB_, j + 1, bf[cur ^ 1]);
            }
            #pragma unroll
            for (int mb = 0; mb < 4; mb++)
                #pragma unroll
                for (int nbb = 0; nbb < 4; nbb++) {
                    mma16816(acc[mb][nbb * 2 + 0], af[cur][mb],
                             bf[cur][nbb][0], bf[cur][nbb][2]);
                    mma16816(acc[mb][nbb * 2 + 1], af[cur][mb],
                             bf[cur][nbb][1], bf[cur][nbb][3]);
                }
        }
    };

    bulk_load(0, 0);
    if (nch > 1) bulk_load(1, 1);
    for (int i = 0; i < nch; i++) {
        __syncthreads();                   // stage (i+2)%3 fully consumed
        if (i + 2 < nch) bulk_load((i + 2) % NSTG, i + 2);
        mbar_wait(mb0 + 8 * (i % NSTG), (i / NSTG) & 1);
        compute(i % NSTG);
    }

    // ----- epilogue -----
    char* d3 = 0;
    int satype = 1, colr = col0;
    float* df = 0;
    int ldf = ldcf;
    long long ztile = 0;
    if (emode == 0) {
        df = Cf + (long long)blockIdx.z * sC;
    } else if (emode == 1) {
        d3 = C3a; ztile = (long long)blockIdx.z * sC;   // sC in tiles
    } else {                                  // qkv triple
        if (col0 < 1024)      { d3 = C3a; satype = 1; colr = col0; }
        else if (col0 < 2048) { d3 = C3b; satype = 0; colr = col0 - 1024; }
        else                  { df = Cv; ldf = 1024; colr = col0 - 2048; }
    }

    const int cbase = wn * 64 + 2 * (lane & 3);
    #pragma unroll
    for (int mb = 0; mb < 4; mb++) {
        #pragma unroll
        for (int half = 0; half < 2; half++) {
            const int r = row0 + wm * 64 + mb * 16 + (lane >> 2) + half * 8;
            char* rowbase = d3 ? (d3 + (size_t)(ztile + (long long)(r >> 7) * nchc)
                                      * TILE_BYTES) : (char*)0;
            const int lr = r & 127;
            #pragma unroll
            for (int nb = 0; nb < 8; nb++) {
                const int cr = colr + cbase + nb * 8;    // region-relative (even)
                const int ca = col0 + cbase + nb * 8;    // absolute (bias)
                float vx = acc[mb][nb][half * 2 + 0] * alpha;
                float vy = acc[mb][nb][half * 2 + 1] * alpha;
                if (bias) { vx += bias[ca]; vy += bias[ca + 1]; }
                if (d3) store3_tiled(rowbase, lr, cr, vx, vy, satype);
                else    *(float2*)(df + (long long)r * ldf + cr) = make_float2(vx, vy);
            }
        }
    }
}

// ---------------------------------------------------------------------------
// fp32 -> 3-term interleaved bf16 split, tiled+swizzled output
//   ATYPE=1: (hi, lo, hi)    ATYPE=0 (B operand): (hi, hi, lo)
// ---------------------------------------------------------------------------
template <int ATYPE>
__global__ void split3_kernel(const float* __restrict__ in,
                              __nv_bfloat16* __restrict__ out,
                              int R, int Cin, int ld, int nchbuf)
{
    const int c8n = Cin >> 3;
    long long idx = (long long)blockIdx.x * blockDim.x + threadIdx.x;
    if (idx >= (long long)R * c8n) return;
    const int r = (int)(idx / c8n);
    const int c = (int)(idx - (long long)r * c8n) * 8;

    const float4 v0 = *(const float4*)(in + (long long)r * ld + c);
    const float4 v1 = *(const float4*)(in + (long long)r * ld + c + 4);
    float f[8] = {v0.x, v0.y, v0.z, v0.w, v1.x, v1.y, v1.z, v1.w};

    alignas(16) unsigned short s[24];
    #pragma unroll
    for (int j = 0; j < 8; j++) {
        __nv_bfloat16 h = __float2bfloat16(f[j]);
        __nv_bfloat16 l = __float2bfloat16(f[j] - __bfloat162float(h));
        unsigned short hu = __bfloat16_as_ushort(h);
        unsigned short lu = __bfloat16_as_ushort(l);
        if (ATYPE) { s[3*j] = hu; s[3*j+1] = lu; s[3*j+2] = hu; }
        else       { s[3*j] = hu; s[3*j+1] = hu; s[3*j+2] = lu; }
    }
    char* rowbase = (char*)out + (size_t)(r >> 7) * nchbuf * TILE_BYTES;
    const int lr = r & 127;
    #pragma unroll
    for (int j = 0; j < 3; j++) {
        const int byte = 6 * c + 16 * j;     // 16B-aligned (c multiple of 8)
        const int ct = byte >> 7;
        const int rem = byte & 127;
        *(uint4*)(rowbase + (size_t)ct * TILE_BYTES + SWB(lr, rem >> 4)) =
            ((uint4*)s)[j];
    }
}

// V[s,c] fp32 [8192,1024] -> vt3 tiled: batch b, row c (0..1023), k'=3s+{0,1,2}
__global__ void transpose_split3_kernel(const float* __restrict__ v,
                                        __nv_bfloat16* __restrict__ vt3)
{
    __shared__ float tile[32][33];
    const int b = blockIdx.z;
    const int s0 = blockIdx.x * 32, c0 = blockIdx.y * 32;
    const int tx = threadIdx.x, ty = threadIdx.y;
    tile[ty][tx] = v[((long long)(b * 2048 + s0 + ty)) * 1024 + c0 + tx];
    __syncthreads();
    const float val = tile[tx][ty];
    __nv_bfloat16 h = __float2bfloat16(val);
    __nv_bfloat16 l = __float2bfloat16(val - __bfloat162float(h));
    unsigned short u[3] = {__bfloat16_as_ushort(h), __bfloat16_as_ushort(h),
                           __bfloat16_as_ushort(l)};
    const int row = c0 + ty;
    const int ss = s0 + tx;
    char* rowbase = (char*)vt3 +
        (size_t)(b * 8 * 96 + (row >> 7) * 96) * TILE_BYTES;
    const int lr = row & 127;
    #pragma unroll
    for (int t = 0; t < 3; t++) {
        const int byte = 6 * ss + 2 * t;
        const int ct = byte >> 7;
        const int rem = byte & 127;
        *(unsigned short*)(rowbase + (size_t)ct * TILE_BYTES
                           + SWB(lr, rem >> 4) + (rem & 15)) = u[t];
    }
}

// ---------------------------------------------------------------------------
// FMA-pipe exp for x <= 0 (MUFU EX2 is quarter-rate on B300).
// ---------------------------------------------------------------------------
__device__ __forceinline__ float fexp(float x) {
    float y = x * 1.4426950408889634f;
    float n = floorf(y);
    float f = y - n;
    float p = 0.000154035304f;
    p = fmaf(p, f, 0.00133335581f);
    p = fmaf(p, f, 0.00961812910f);
    p = fmaf(p, f, 0.0555041087f);
    p = fmaf(p, f, 0.240226507f);
    p = fmaf(p, f, 0.693147180f);
    p = fmaf(p, f, 1.0f);
    int ni = (int)n;
    if (ni < -126) return 0.f;
    return p * __int_as_float((ni + 127) << 23);
}

// ---------------------------------------------------------------------------
// causal softmax: fp32 scores -> A-split bf16 att3 (tiled), zeros masked tail
// ---------------------------------------------------------------------------
__global__ void softmax_split_kernel(const float* __restrict__ att,
                                     __nv_bfloat16* __restrict__ att3, int Tn)
{
    __shared__ float buf[2048];
    __shared__ float red[256];
    const int row = blockIdx.x;
    const int t = row % Tn;
    const float* p = att + (long long)row * Tn;
    const int tid = threadIdx.x;
    const int len = t + 1;

    float m = -1e30f;
    for (int s = tid; s < len; s += 256) { float v = p[s]; buf[s] = v; m = fmaxf(m, v); }
    red[tid] = m; __syncthreads();
    for (int off = 128; off > 0; off >>= 1) {
        if (tid < off) red[tid] = fmaxf(red[tid], red[tid + off]);
        __syncthreads();
    }
    m = red[0]; __syncthreads();

    float sum = 0.f;
    for (int s = tid; s < len; s += 256) {
        float e = fexp(buf[s] - m);
        buf[s] = e;
        sum += e;
    }
    red[tid] = sum; __syncthreads();
    for (int off = 128; off > 0; off >>= 1) {
        if (tid < off) red[tid] += red[tid + off];
        __syncthreads();
    }
    const float inv = 1.f / red[0];
    __syncthreads();

    const int s8 = tid * 8;               // 256*8 == Tn: one pass per row
    alignas(16) unsigned short sh[24];
    #pragma unroll
    for (int j = 0; j < 8; j++) {
        const int s = s8 + j;
        const float e = (s < len) ? buf[s] * inv : 0.f;
        __nv_bfloat16 h = __float2bfloat16(e);
        __nv_bfloat16 l = __float2bfloat16(e - __bfloat162float(h));
        sh[3*j] = __bfloat16_as_ushort(h);
        sh[3*j+1] = __bfloat16_as_ushort(l);
        sh[3*j+2] = __bfloat16_as_ushort(h);
    }
    char* rowbase = (char*)att3 + (size_t)(row >> 7) * 96 * TILE_BYTES;
    const int lr = row & 127;
    #pragma unroll
    for (int j = 0; j < 3; j++) {
        const int byte = 6 * s8 + 16 * j;
        const int ct = byte >> 7;
        const int rem = byte & 127;
        *(uint4*)(rowbase + (size_t)ct * TILE_BYTES + SWB(lr, rem >> 4)) =
            ((uint4*)sh)[j];
    }
}

// ---------------------------------------------------------------------------
extern "C" void kernel_launch(void* const* d_in, const int* in_sizes, int n_in,
                              void* d_out, int out_size)
{
    const float* x      = (const float*)d_in[0];
    const float* w_qkv  = (const float*)d_in[1];
    const float* b_qkv  = (const float*)d_in[2];
    const float* w_proj = (const float*)d_in[3];
    const float* b_proj = (const float*)d_in[4];
    float* out = (float*)d_out;

    float *att, *v;
    __nv_bfloat16 *x3, *wqkv3, *wproj3, *q3, *k3, *vt3, *att3, *o3;
    cudaGetSymbolAddress((void**)&att, g_att);
    cudaGetSymbolAddress((void**)&v,   g_v);
    cudaGetSymbolAddress((void**)&x3,    g_x3);
    cudaGetSymbolAddress((void**)&wqkv3, g_wqkv3);
    cudaGetSymbolAddress((void**)&wproj3,g_wproj3);
    cudaGetSymbolAddress((void**)&q3,    g_q3);
    cudaGetSymbolAddress((void**)&k3,    g_k3);
    cudaGetSymbolAddress((void**)&vt3,   g_vt3);
    cudaGetSymbolAddress((void**)&att3,  g_att3);
    cudaGetSymbolAddress((void**)&o3,    g_o3);

    cudaFuncSetAttribute(hmma_gemm,
        cudaFuncAttributeMaxDynamicSharedMemorySize, GEMM_SMEM);

    const float inv_sqrt_c = 0.03125f;

    // split the raw inputs into tiled split-bf16
    split3_kernel<1><<<(M * (C / 8) + 255) / 256, 256>>>(x, x3, M, C, C, 48);
    split3_kernel<0><<<(3 * C * (C / 8) + 255) / 256, 256>>>(w_qkv, wqkv3, 3 * C, C, C, 48);
    split3_kernel<0><<<(C * (C / 8) + 255) / 256, 256>>>(w_proj, wproj3, C, C, C, 48);

    // 1) qkv GEMM -> q3 (A-split tiled) / k3 (B-split tiled) / v (fp32)
    hmma_gemm<<<dim3(3 * C / 128, M / 128, 1), 128, GEMM_SMEM>>>(
        (const char*)x3, (const char*)wqkv3, nullptr,
        (char*)q3, (char*)k3, v,
        48, 48, 0, 48, 0, 0, 0,
        1.f, b_qkv, 0, 0, K3C, 2);

    // transpose-split v -> vt3 (B-type, tiled)
    transpose_split3_kernel<<<dim3(T / 32, C / 32, Bb), dim3(32, 32)>>>(v, vt3);

    // 2) scores = (q @ k^T) / sqrt(C), causal tile-skip, fp32 out
    hmma_gemm<<<dim3(T / 128, T / 128, Bb), 128, GEMM_SMEM>>>(
        (const char*)q3, (const char*)k3, att, nullptr, nullptr, nullptr,
        48, 48, T, 0,
        16 * 48, 16 * 48, (long long)T * T,
        inv_sqrt_c, nullptr, 1, 0, K3C, 0);

    // 3) softmax fused with A-split -> att3 (tiled, zeros masked tail)
    softmax_split_kernel<<<M, 256>>>(att, att3, T);

    // 4) o = att @ V  (k-limited) -> o3 (A-split tiled)
    hmma_gemm<<<dim3(C / 128, T / 128, Bb), 128, GEMM_SMEM>>>(
        (const char*)att3, (const char*)vt3, nullptr,
        (char*)o3, nullptr, nullptr,
        96, 96, 0, 48,
        16 * 96, 8 * 96, 16 * 48,
        1.f, nullptr, 0, 1, K3T, 1);

    // 5) out = o @ w_proj^T + b_proj   (fp32 out)
    hmma_gemm<<<dim3(C / 128, M / 128, 1), 128, GEMM_SMEM>>>(
        (const char*)o3, (const char*)wproj3, out, nullptr, nullptr, nullptr,
        48, 48, C, 0, 0, 0, 0,
        1.f, b_proj, 0, 0, K3C, 0);
}

// round 10
// speedup vs baseline: 1.1520x; 1.0281x over previous
#include <cuda_runtime.h>
#include <cuda_bf16.h>
#include <math.h>

// ---------------------------------------------------------------------------
// Causal self-attention block via mma.sync (HMMA bf16) on sm_103.
// fp32 emulation by SEGMENTED 2-plane bf16 split: every operand stored as
// (H, L) tiled planes over original K; GEMM computes AhBh + AlBh + AhBl
// (drops only AlBl ~2^-18). Same HMMA count as 3-term interleave but 1/3
// less traffic (bulk, LDSM, splits, epilogues, softmax).
// R10: planes are pre-swizzled 8KB tiles [128 rows x 32 k]; stages loaded
// with 4x cp.async.bulk; 3-stage pipeline.
// ---------------------------------------------------------------------------

static const int Bb = 4, T = 2048, C = 1024;
static const int M = Bb * T;          // 8192

#define TILE32 8192                   // 128 rows x 32 k x 2B

// fp32 intermediates
__device__ float g_att[(size_t)4 * 2048 * 2048];
__device__ float g_v  [(size_t)8192 * 1024];
// (H,L) bf16 planes, tiled [row_stripe][chunk][8KB swizzled]
__device__ __nv_bfloat16 g_xH [(size_t)8192 * 1024];
__device__ __nv_bfloat16 g_xL [(size_t)8192 * 1024];
__device__ __nv_bfloat16 g_wqH[(size_t)3072 * 1024];
__device__ __nv_bfloat16 g_wqL[(size_t)3072 * 1024];
__device__ __nv_bfloat16 g_wpH[(size_t)1024 * 1024];
__device__ __nv_bfloat16 g_wpL[(size_t)1024 * 1024];
__device__ __nv_bfloat16 g_qH [(size_t)8192 * 1024];
__device__ __nv_bfloat16 g_qL [(size_t)8192 * 1024];
__device__ __nv_bfloat16 g_kH [(size_t)8192 * 1024];
__device__ __nv_bfloat16 g_kL [(size_t)8192 * 1024];
__device__ __nv_bfloat16 g_vtH[(size_t)4 * 1024 * 2048];
__device__ __nv_bfloat16 g_vtL[(size_t)4 * 1024 * 2048];
__device__ __nv_bfloat16 g_aH [(size_t)8192 * 2048];
__device__ __nv_bfloat16 g_aL [(size_t)8192 * 2048];
__device__ __nv_bfloat16 g_oH [(size_t)8192 * 1024];
__device__ __nv_bfloat16 g_oL [(size_t)8192 * 1024];

// swizzle for 64-byte rows (32 bf16): 16B slot c (0..3) -> c ^ ((r>>1)&3)
// (8-row ldmatrix phase spans 2 x 128B bank cycles; (r>>1) makes the 4 rows
// sharing a 128B phase hit 4 distinct 16B banks)
#define SWB32(r, c) ((unsigned)((r) * 64 + ((((c) ^ (((r) >> 1) & 3)) & 3) << 4)))

__device__ __forceinline__ void ldm4(unsigned* r, unsigned addr) {
    asm volatile("ldmatrix.sync.aligned.m8n8.x4.shared.b16 {%0,%1,%2,%3}, [%4];"
        : "=r"(r[0]), "=r"(r[1]), "=r"(r[2]), "=r"(r[3]) : "r"(addr));
}
__device__ __forceinline__ void mma16816(float* d, const unsigned* a,
                                         unsigned b0, unsigned b1) {
    asm volatile(
        "mma.sync.aligned.m16n8k16.row.col.f32.bf16.bf16.f32 "
        "{%0,%1,%2,%3}, {%4,%5,%6,%7}, {%8,%9}, {%0,%1,%2,%3};"
        : "+f"(d[0]), "+f"(d[1]), "+f"(d[2]), "+f"(d[3])
        : "r"(a[0]), "r"(a[1]), "r"(a[2]), "r"(a[3]), "r"(b0), "r"(b1));
}
__device__ __forceinline__ void bulk8k(unsigned sdst, const void* g, unsigned mb) {
    unsigned sz = TILE32;
    asm volatile(
        "cp.async.bulk.shared::cluster.global.mbarrier::complete_tx::bytes "
        "[%0], [%1], %2, [%3];"
        :: "r"(sdst), "l"(__cvta_generic_to_global(g)), "r"(sz), "r"(mb)
        : "memory");
}
__device__ __forceinline__ void mbar_wait(unsigned mbar, unsigned parity) {
    asm volatile(
        "{\n\t.reg .pred P;\n\t"
        "LW_%=:\n\t"
        "mbarrier.try_wait.parity.acquire.cta.shared::cta.b64 P, [%0], %1, 0x989680;\n\t"
        "@P bra.uni LD_%=;\n\t"
        "bra.uni LW_%=;\n\t"
        "LD_%=:\n\t}"
        :: "r"(mbar), "r"(parity) : "memory");
}

// split v into (h,l)
__device__ __forceinline__ void split2(float v, unsigned short& h, unsigned short& l) {
    __nv_bfloat16 hb = __float2bfloat16(v);
    __nv_bfloat16 lb = __float2bfloat16(v - __bfloat162float(hb));
    h = __bfloat16_as_ushort(hb);
    l = __bfloat16_as_ushort(lb);
}

#define STAGE_BYTES 32768 // Ah 8K + Al 8K + Bh 8K + Bl 8K
#define NSTG 3
#define GEMM_SMEM (NSTG * STAGE_BYTES + 128)

// ---------------------------------------------------------------------------
// D[M,N] = alpha * (AhBh + AlBh + AhBl)^T-style split GEMM (+ bias)
// 128 threads, 4 warps, 64x64 warp tiles over a 128x128 CTA tile.
// ncha/nchb: chunks per row-stripe; sAt/sBt: batch strides (tiles).
// emode 0: fp32 out (Cf, ldcf, batch stride sC elems)
// emode 1: plane out D1H/D1L (nchc chunks/stripe, batch stride sC tiles)
// emode 2: qkv triple: col<1024 -> D1 planes, <2048 -> D2 planes,
//          else fp32 -> Cv (ld 1024). bias indexed by absolute col.
// ---------------------------------------------------------------------------
__global__ void __launch_bounds__(128, 2)
hmma_gemm(const char* __restrict__ AH, const char* __restrict__ AL,
          const char* __restrict__ BH, const char* __restrict__ BL,
          float* __restrict__ Cf,
          char* __restrict__ D1H, char* __restrict__ D1L,
          char* __restrict__ D2H, char* __restrict__ D2L,
          float* __restrict__ Cv,
          int ncha, int nchb, int ldcf, int nchc,
          long long sAt, long long sBt, long long sC,
          float alpha, const float* __restrict__ bias,
          int causal_skip, int klimit, int K, int emode)
{
    const int row0 = blockIdx.y * 128;
    const int col0 = blockIdx.x * 128;
    if (causal_skip && col0 > row0) return;              // strictly-upper tiles
    const int kend = klimit ? min(K, row0 + 128) : K;
    const int nch = kend >> 5;                           // 32-k chunks

    const long long aoff = ((long long)blockIdx.z * sAt + (row0 >> 7) * ncha) * TILE32;
    const long long boff = ((long long)blockIdx.z * sBt + (col0 >> 7) * nchb) * TILE32;
    AH += aoff; AL += aoff; BH += boff; BL += boff;

    extern __shared__ __align__(128) unsigned char smem[];
    const unsigned sb = (unsigned)__cvta_generic_to_shared(smem);
    const unsigned mb0 = sb + NSTG * STAGE_BYTES;        // 3 mbarriers

    const int tid = threadIdx.x;
    const int lane = tid & 31;
    const int wid = tid >> 5;          // 0..3
    const int wm = wid >> 1;           // 0..1 -> 64-row half
    const int wn = wid & 1;            // 0..1 -> 64-col half

    if (tid == 0) {
        #pragma unroll
        for (int s = 0; s < NSTG; s++)
            asm volatile("mbarrier.init.shared.b64 [%0], 1;"
                         :: "r"(mb0 + 8 * s) : "memory");
    }
    __syncthreads();

    float acc[4][8][4];
    #pragma unroll
    for (int i = 0; i < 4; i++)
        #pragma unroll
        for (int j = 0; j < 8; j++)
            #pragma unroll
            for (int k = 0; k < 4; k++) acc[i][j][k] = 0.f;

    auto bulk_load = [&](int st, int chunk) {
        if (tid == 0) {
            const unsigned mb = mb0 + 8 * st;
            asm volatile("mbarrier.arrive.expect_tx.shared.b64 _, [%0], %1;"
                         :: "r"(mb), "r"((unsigned)STAGE_BYTES) : "memory");
            const unsigned s0 = sb + st * STAGE_BYTES;
            const size_t co = (size_t)chunk * TILE32;
            bulk8k(s0,          AH + co, mb);
            bulk8k(s0 + 8192,   AL + co, mb);
            bulk8k(s0 + 16384,  BH + co, mb);
            bulk8k(s0 + 24576,  BL + co, mb);
        }
    };

    auto compute = [&](int st) {
        const unsigned s0 = sb + st * STAGE_BYTES;
        #pragma unroll
        for (int s = 0; s < 2; s++) {                    // two k16 slices
            const int ch = 2 * s + (lane >> 4);
            unsigned AhF[4][4], AlF[4][4], BhF[4][4], BlF[4][4];
            #pragma unroll
            for (int mb = 0; mb < 4; mb++) {
                const int mr = wm * 64 + mb * 16 + (lane & 15);
                ldm4(AhF[mb], s0 +         SWB32(mr, ch));
                ldm4(AlF[mb], s0 + 8192  + SWB32(mr, ch));
            }
            #pragma unroll
            for (int nb = 0; nb < 4; nb++) {
                const int nr = wn * 64 + nb * 16 + (lane & 15);
                ldm4(BhF[nb], s0 + 16384 + SWB32(nr, ch));
                ldm4(BlF[nb], s0 + 24576 + SWB32(nr, ch));
            }
            // product 1: Ah * Bh
            #pragma unroll
            for (int mb = 0; mb < 4; mb++)
                #pragma unroll
                for (int nb = 0; nb < 4; nb++) {
                    mma16816(acc[mb][nb * 2 + 0], AhF[mb], BhF[nb][0], BhF[nb][2]);
                    mma16816(acc[mb][nb * 2 + 1], AhF[mb], BhF[nb][1], BhF[nb][3]);
                }
            // product 2: Al * Bh
            #pragma unroll
            for (int mb = 0; mb < 4; mb++)
                #pragma unroll
                for (int nb = 0; nb < 4; nb++) {
                    mma16816(acc[mb][nb * 2 + 0], AlF[mb], BhF[nb][0], BhF[nb][2]);
                    mma16816(acc[mb][nb * 2 + 1], AlF[mb], BhF[nb][1], BhF[nb][3]);
                }
            // product 3: Ah * Bl
            #pragma unroll
            for (int mb = 0; mb < 4; mb++)
                #pragma unroll
                for (int nb = 0; nb < 4; nb++) {
                    mma16816(acc[mb][nb * 2 + 0], AhF[mb], BlF[nb][0], BlF[nb][2]);
                    mma16816(acc[mb][nb * 2 + 1], AhF[mb], BlF[nb][1], BlF[nb][3]);
                }
        }
    };

    bulk_load(0, 0);
    if (nch > 1) bulk_load(1, 1);
    for (int i = 0; i < nch; i++) {
        __syncthreads();                   // stage (i+2)%3 fully consumed
        if (i + 2 < nch) bulk_load((i + 2) % NSTG, i + 2);
        mbar_wait(mb0 + 8 * (i % NSTG), (i / NSTG) & 1);
        compute(i % NSTG);
    }

    // ----- epilogue -----
    char *dH = 0, *dL = 0;
    int colr = col0;
    float* df = 0;
    int ldf = ldcf;
    long long ztile = 0;
    if (emode == 0) {
        df = Cf + (long long)blockIdx.z * sC;
    } else if (emode == 1) {
        dH = D1H; dL = D1L; ztile = (long long)blockIdx.z * sC;   // sC in tiles
    } else {                                  // qkv triple
        if (col0 < 1024)      { dH = D1H; dL = D1L; colr = col0; }
        else if (col0 < 2048) { dH = D2H; dL = D2L; colr = col0 - 1024; }
        else                  { df = Cv; ldf = 1024; colr = col0 - 2048; }
    }

    const int cbase = wn * 64 + 2 * (lane & 3);
    #pragma unroll
    for (int mb = 0; mb < 4; mb++) {
        #pragma unroll
        for (int half = 0; half < 2; half++) {
            const int r = row0 + wm * 64 + mb * 16 + (lane >> 2) + half * 8;
            const long long tb = dH ? (ztile + (long long)(r >> 7) * nchc) * TILE32 : 0;
            const int lr = r & 127;
            #pragma unroll
            for (int nb = 0; nb < 8; nb++) {
                const int cr = colr + cbase + nb * 8;    // region-relative (even)
                const int ca = col0 + cbase + nb * 8;    // absolute (bias)
                float vx = acc[mb][nb][half * 2 + 0] * alpha;
                float vy = acc[mb][nb][half * 2 + 1] * alpha;
                if (bias) { vx += bias[ca]; vy += bias[ca + 1]; }
                if (dH) {
                    unsigned short hx, lx, hy, ly;
                    split2(vx, hx, lx);
                    split2(vy, hy, ly);
                    const int byte = 2 * cr;             // multiple of 4
                    const unsigned off = (unsigned)(byte >> 6) * TILE32
                                       + SWB32(lr, (byte & 63) >> 4) + (byte & 15);
                    *(unsigned*)(dH + tb + off) = (unsigned)hx | ((unsigned)hy << 16);
                    *(unsigned*)(dL + tb + off) = (unsigned)lx | ((unsigned)ly << 16);
                } else {
                    *(float2*)(df + (long long)r * ldf + cr) = make_float2(vx, vy);
                }
            }
        }
    }
}

// ---------------------------------------------------------------------------
// fp32 -> (h,l) planes, tiled+swizzled output
// ---------------------------------------------------------------------------
__global__ void split2_kernel(const float* __restrict__ in,
                              __nv_bfloat16* __restrict__ outH,
                              __nv_bfloat16* __restrict__ outL,
                              int R, int Cin, int ld)
{
    const int c8n = Cin >> 3;
    long long idx = (long long)blockIdx.x * blockDim.x + threadIdx.x;
    if (idx >= (long long)R * c8n) return;
    const int r = (int)(idx / c8n);
    const int c = (int)(idx - (long long)r * c8n) * 8;

    const float4 v0 = *(const float4*)(in + (long long)r * ld + c);
    const float4 v1 = *(const float4*)(in + (long long)r * ld + c + 4);
    float f[8] = {v0.x, v0.y, v0.z, v0.w, v1.x, v1.y, v1.z, v1.w};

    alignas(16) unsigned short h[8], l[8];
    #pragma unroll
    for (int j = 0; j < 8; j++) split2(f[j], h[j], l[j]);

    const int nch = Cin >> 5;
    const size_t base = (size_t)(r >> 7) * nch * TILE32;
    const int lr = r & 127;
    const int byte = 2 * c;                   // multiple of 16
    const unsigned off = (unsigned)(byte >> 6) * TILE32
                       + SWB32(lr, (byte & 63) >> 4);
    *(uint4*)((char*)outH + base + off) = *(uint4*)h;
    *(uint4*)((char*)outL + base + off) = *(uint4*)l;
}

// V[s,c] fp32 [8192,1024] -> vt planes: batch b, row=channel, k=token
__global__ void transpose_split2_kernel(const float* __restrict__ v,
                                        __nv_bfloat16* __restrict__ vtH,
                                        __nv_bfloat16* __restrict__ vtL)
{
    __shared__ float tile[32][33];
    const int b = blockIdx.z;
    const int s0 = blockIdx.x * 32, c0 = blockIdx.y * 32;
    const int tx = threadIdx.x, ty = threadIdx.y;
    tile[ty][tx] = v[((long long)(b * 2048 + s0 + ty)) * 1024 + c0 + tx];
    __syncthreads();
    unsigned short h, l;
    split2(tile[tx][ty], h, l);
    const int row = c0 + ty;                  // channel 0..1023
    const int ss = s0 + tx;                   // token
    const size_t base = (size_t)(b * 8 * 64 + (row >> 7) * 64) * TILE32;
    const int lr = row & 127;
    const int byte = 2 * ss;
    const unsigned off = (unsigned)(byte >> 6) * TILE32
                       + SWB32(lr, (byte & 63) >> 4) + (byte & 15);
    *(unsigned short*)((char*)vtH + base + off) = h;
    *(unsigned short*)((char*)vtL + base + off) = l;
}

// ---------------------------------------------------------------------------
// FMA-pipe exp for x <= 0 (MUFU EX2 is quarter-rate on B300).
// ---------------------------------------------------------------------------
__device__ __forceinline__ float fexp(float x) {
    float y = x * 1.4426950408889634f;
    float n = floorf(y);
    float f = y - n;
    float p = 0.000154035304f;
    p = fmaf(p, f, 0.00133335581f);
    p = fmaf(p, f, 0.00961812910f);
    p = fmaf(p, f, 0.0555041087f);
    p = fmaf(p, f, 0.240226507f);
    p = fmaf(p, f, 0.693147180f);
    p = fmaf(p, f, 1.0f);
    int ni = (int)n;
    if (ni < -126) return 0.f;
    return p * __int_as_float((ni + 127) << 23);
}

// ---------------------------------------------------------------------------
// causal softmax: fp32 scores -> (h,l) att planes (tiled). Only writes up to
// the 128-rounded row boundary (exactly what att@V's k-limit reads).
// ---------------------------------------------------------------------------
__global__ void softmax_split_kernel(const float* __restrict__ att,
                                     __nv_bfloat16* __restrict__ attH,
                                     __nv_bfloat16* __restrict__ attL, int Tn)
{
    __shared__ float buf[2048];
    __shared__ float red[256];
    const int row = blockIdx.x;
    const int t = row % Tn;
    const float* p = att + (long long)row * Tn;
    const int tid = threadIdx.x;
    const int len = t + 1;
    const int lenR = (t & ~127) + 128;        // = row-tile boundary

    float m = -1e30f;
    for (int s = tid; s < len; s += 256) { float v = p[s]; buf[s] = v; m = fmaxf(m, v); }
    red[tid] = m; __syncthreads();
    for (int off = 128; off > 0; off >>= 1) {
        if (tid < off) red[tid] = fmaxf(red[tid], red[tid + off]);
        __syncthreads();
    }
    m = red[0]; __syncthreads();

    float sum = 0.f;
    for (int s = tid; s < len; s += 256) {
        float e = fexp(buf[s] - m);
        buf[s] = e;
        sum += e;
    }
    red[tid] = sum; __syncthreads();
    for (int off = 128; off > 0; off >>= 1) {
        if (tid < off) red[tid] += red[tid + off];
        __syncthreads();
    }
    const float inv = 1.f / red[0];
    __syncthreads();

    const int s8 = tid * 8;                   // 8 tokens per thread
    if (s8 < lenR) {
        alignas(16) unsigned short h[8], l[8];
        #pragma unroll
        for (int j = 0; j < 8; j++) {
            const int s = s8 + j;
            const float e = (s < len) ? buf[s] * inv : 0.f;
            split2(e, h[j], l[j]);
        }
        const size_t base = (size_t)(row >> 7) * 64 * TILE32;
        const int lr = row & 127;
        const int byte = 2 * s8;
        const unsigned off = (unsigned)(byte >> 6) * TILE32
                           + SWB32(lr, (byte & 63) >> 4);
        *(uint4*)((char*)attH + base + off) = *(uint4*)h;
        *(uint4*)((char*)attL + base + off) = *(uint4*)l;
    }
}

// ---------------------------------------------------------------------------
extern "C" void kernel_launch(void* const* d_in, const int* in_sizes, int n_in,
                              void* d_out, int out_size)
{
    const float* x      = (const float*)d_in[0];
    const float* w_qkv  = (const float*)d_in[1];
    const float* b_qkv  = (const float*)d_in[2];
    const float* w_proj = (const float*)d_in[3];
    const float* b_proj = (const float*)d_in[4];
    float* out = (float*)d_out;

    float *att, *v;
    __nv_bfloat16 *xH, *xL, *wqH, *wqL, *wpH, *wpL;
    __nv_bfloat16 *qH, *qL, *kH, *kL, *vtH, *vtL, *aH, *aL, *oH, *oL;
    cudaGetSymbolAddress((void**)&att, g_att);
    cudaGetSymbolAddress((void**)&v,   g_v);
    cudaGetSymbolAddress((void**)&xH,  g_xH);  cudaGetSymbolAddress((void**)&xL,  g_xL);
    cudaGetSymbolAddress((void**)&wqH, g_wqH); cudaGetSymbolAddress((void**)&wqL, g_wqL);
    cudaGetSymbolAddress((void**)&wpH, g_wpH); cudaGetSymbolAddress((void**)&wpL, g_wpL);
    cudaGetSymbolAddress((void**)&qH,  g_qH);  cudaGetSymbolAddress((void**)&qL,  g_qL);
    cudaGetSymbolAddress((void**)&kH,  g_kH);  cudaGetSymbolAddress((void**)&kL,  g_kL);
    cudaGetSymbolAddress((void**)&vtH, g_vtH); cudaGetSymbolAddress((void**)&vtL, g_vtL);
    cudaGetSymbolAddress((void**)&aH,  g_aH);  cudaGetSymbolAddress((void**)&aL,  g_aL);
    cudaGetSymbolAddress((void**)&oH,  g_oH);  cudaGetSymbolAddress((void**)&oL,  g_oL);

    cudaFuncSetAttribute(hmma_gemm,
        cudaFuncAttributeMaxDynamicSharedMemorySize, GEMM_SMEM);

    const float inv_sqrt_c = 0.03125f;

    // split the raw inputs into (h,l) planes
    split2_kernel<<<(M * (C / 8) + 255) / 256, 256>>>(x, xH, xL, M, C, C);
    split2_kernel<<<(3 * C * (C / 8) + 255) / 256, 256>>>(w_qkv, wqH, wqL, 3 * C, C, C);
    split2_kernel<<<(C * (C / 8) + 255) / 256, 256>>>(w_proj, wpH, wpL, C, C, C);

    // 1) qkv GEMM -> q planes / k planes / v (fp32)
    hmma_gemm<<<dim3(3 * C / 128, M / 128, 1), 128, GEMM_SMEM>>>(
        (const char*)xH, (const char*)xL, (const char*)wqH, (const char*)wqL,
        nullptr, (char*)qH, (char*)qL, (char*)kH, (char*)kL, v,
        32, 32, 0, 32, 0, 0, 0,
        1.f, b_qkv, 0, 0, C, 2);

    // transpose-split v -> vt planes
    transpose_split2_kernel<<<dim3(T / 32, C / 32, Bb), dim3(32, 32)>>>(v, vtH, vtL);

    // 2) scores = (q @ k^T) / sqrt(C), causal tile-skip, fp32 out
    hmma_gemm<<<dim3(T / 128, T / 128, Bb), 128, GEMM_SMEM>>>(
        (const char*)qH, (const char*)qL, (const char*)kH, (const char*)kL,
        att, nullptr, nullptr, nullptr, nullptr, nullptr,
        32, 32, T, 0,
        16 * 32, 16 * 32, (long long)T * T,
        inv_sqrt_c, nullptr, 1, 0, C, 0);

    // 3) softmax -> att planes (tile-bounded writes)
    softmax_split_kernel<<<M, 256>>>(att, aH, aL, T);

    // 4) o = att @ V  (k-limited) -> o planes
    hmma_gemm<<<dim3(C / 128, T / 128, Bb), 128, GEMM_SMEM>>>(
        (const char*)aH, (const char*)aL, (const char*)vtH, (const char*)vtL,
        nullptr, (char*)oH, (char*)oL, nullptr, nullptr, nullptr,
        64, 64, 0, 32,
        16 * 64, 8 * 64, 16 * 32,
        1.f, nullptr, 0, 1, T, 1);

    // 5) out = o @ w_proj^T + b_proj   (fp32 out)
    hmma_gemm<<<dim3(C / 128, M / 128, 1), 128, GEMM_SMEM>>>(
        (const char*)oH, (const char*)oL, (const char*)wpH, (const char*)wpL,
        out, nullptr, nullptr, nullptr, nullptr, nullptr,
        32, 32, C, 0, 0, 0, 0,
        1.f, b_proj, 0, 0, C, 0);
}